// round 6
// baseline (speedup 1.0000x reference)
#include <cuda_runtime.h>
#include <cuda_bf16.h>
#include <math.h>
#include <stdint.h>

// Problem constants
#define T_STEPS 16
#define BATCH   128
#define IN_DIM  12288
#define H1_DIM  256
#define H2_DIM  512

#define RGRID 256        // persistent recurrence grid (must be <= guaranteed-resident)

// ---------------------------------------------------------------------------
// Device-global scratch (no allocation allowed)
// ---------------------------------------------------------------------------
__device__ __align__(256) __nv_bfloat16 g_Xhi [2048 * 12288];
__device__ __align__(256) __nv_bfloat16 g_Xlo [2048 * 12288];
__device__ __align__(256) __nv_bfloat16 g_W1hi[1024 * 12288];
__device__ __align__(256) __nv_bfloat16 g_W1lo[1024 * 12288];
__device__ __align__(256) __nv_bfloat16 g_W2hi[2048 * 256];
__device__ __align__(256) __nv_bfloat16 g_W2lo[2048 * 256];
__device__ __align__(256) __nv_bfloat16 g_y1hi[2048 * 256];
__device__ __align__(256) __nv_bfloat16 g_y1lo[2048 * 256];

__device__ float g_pre1 [2048 * 1024];    // [T*B, 4*H1]
__device__ float g_pre2 [2048 * 2048];    // [T*B, 4*H2]
__device__ float g_h1[2][128 * 256];
__device__ float g_c1[128 * 256];
__device__ float g_h2[2][128 * 512];
__device__ float g_c2[128 * 512];

// software grid barrier state (zero-initialized; self-resetting)
__device__ unsigned g_bar_cnt;
__device__ unsigned g_bar_gen;

__device__ __forceinline__ float sigmoidf_(float x) {
    return 1.0f / (1.0f + expf(-x));
}

// ---------------------------------------------------------------------------
// PTX helpers (compute_103-safe: cp.async + ldmatrix + mma.sync only)
// ---------------------------------------------------------------------------
__device__ __forceinline__ uint32_t smem_u32(const void* p) {
    uint32_t a;
    asm("{ .reg .u64 t; cvta.to.shared.u64 t, %1; cvt.u32.u64 %0, t; }"
        : "=r"(a) : "l"(p));
    return a;
}

template <int N>
__device__ __forceinline__ void cpwait() {
    asm volatile("cp.async.wait_group %0;" :: "n"(N));
}

__device__ __forceinline__ void cp16(uint32_t dst, const void* src) {
    asm volatile("cp.async.cg.shared.global [%0], [%1], 16;"
                 :: "r"(dst), "l"(src));
}

__device__ __forceinline__ void cpcommit() {
    asm volatile("cp.async.commit_group;");
}

__device__ __forceinline__ void ldsm4(uint32_t* r, uint32_t addr) {
    asm volatile("ldmatrix.sync.aligned.m8n8.x4.shared.b16 {%0,%1,%2,%3}, [%4];"
                 : "=r"(r[0]), "=r"(r[1]), "=r"(r[2]), "=r"(r[3]) : "r"(addr));
}

__device__ __forceinline__ void mma_bf16(float* d, const uint32_t* a,
                                         uint32_t b0, uint32_t b1) {
    asm volatile(
        "mma.sync.aligned.m16n8k16.row.col.f32.bf16.bf16.f32 "
        "{%0,%1,%2,%3}, {%4,%5,%6,%7}, {%8,%9}, {%0,%1,%2,%3};"
        : "+f"(d[0]), "+f"(d[1]), "+f"(d[2]), "+f"(d[3])
        : "r"(a[0]), "r"(a[1]), "r"(a[2]), "r"(a[3]), "r"(b0), "r"(b1));
}

// grid-wide barrier: all RGRID blocks arrive; release via generation bump.
__device__ __forceinline__ void grid_barrier(unsigned target) {
    __syncthreads();
    if (threadIdx.x == 0) {
        __threadfence();
        unsigned a = atomicAdd(&g_bar_cnt, 1u);
        if (a == (unsigned)(RGRID - 1)) {
            g_bar_cnt = 0;
            __threadfence();
            atomicAdd(&g_bar_gen, 1u);
        } else {
            volatile unsigned* gp = &g_bar_gen;
            while ((int)(*gp - target) < 0) { }
        }
        __threadfence();
    }
    __syncthreads();
}

// ---------------------------------------------------------------------------
// Zero the recurrent states
// ---------------------------------------------------------------------------
__global__ void zero_states_kernel() {
    int i = blockIdx.x * blockDim.x + threadIdx.x;
    if (i < 128 * 256) { g_h1[0][i] = 0.0f; g_c1[i] = 0.0f; }
    if (i < 128 * 512) { g_h2[0][i] = 0.0f; g_c2[i] = 0.0f; }
}

// ---------------------------------------------------------------------------
// fp32 -> (hi, lo) bf16 split
// ---------------------------------------------------------------------------
__global__ void split_kernel(const float* __restrict__ x,
                             __nv_bfloat16* __restrict__ hi,
                             __nv_bfloat16* __restrict__ lo, int n4) {
    int i = blockIdx.x * blockDim.x + threadIdx.x;
    if (i >= n4) return;
    float4 v = ((const float4*)x)[i];
    __nv_bfloat16 h0 = __float2bfloat16(v.x);
    __nv_bfloat16 h1 = __float2bfloat16(v.y);
    __nv_bfloat16 h2 = __float2bfloat16(v.z);
    __nv_bfloat16 h3 = __float2bfloat16(v.w);
    __nv_bfloat16 l0 = __float2bfloat16(v.x - __bfloat162float(h0));
    __nv_bfloat16 l1 = __float2bfloat16(v.y - __bfloat162float(h1));
    __nv_bfloat16 l2 = __float2bfloat16(v.z - __bfloat162float(h2));
    __nv_bfloat16 l3 = __float2bfloat16(v.w - __bfloat162float(h3));
    ((__nv_bfloat162*)hi)[i * 2 + 0] = __nv_bfloat162(h0, h1);
    ((__nv_bfloat162*)hi)[i * 2 + 1] = __nv_bfloat162(h2, h3);
    ((__nv_bfloat162*)lo)[i * 2 + 0] = __nv_bfloat162(l0, l1);
    ((__nv_bfloat162*)lo)[i * 2 + 1] = __nv_bfloat162(l2, l3);
}

// ---------------------------------------------------------------------------
// Split-bf16 HMMA GEMM: C[m][n] = sum_k A[m][k]*B[n][k]  (fp32 accum/result)
// Tile 128x128x32, 3-stage cp.async pipeline, 256 threads (8 warps, 2x4),
// warp tile 64x32, mma.sync.m16n8k16.bf16. grid = (N/128, M/128).
// ---------------------------------------------------------------------------
#define GSTAGES 3
#define TILE_B 8192                       // one 128x32 bf16 tile
#define GSTAGE_BYTES (4 * TILE_B)         // Ah, Al, Bh, Bl
#define GSMEM_TOTAL (GSTAGES * GSTAGE_BYTES)

// swizzled offset of (row, chunk) within an 8KB tile; chunk = 16B = 8 bf16
__device__ __forceinline__ uint32_t swz(int row, int c) {
    return (uint32_t)(row * 64 + 16 * (c ^ ((row >> 1) & 3)));
}

__global__ __launch_bounds__(256) void gemm_bf16split(
    const __nv_bfloat16* __restrict__ Ahi, const __nv_bfloat16* __restrict__ Alo,
    const __nv_bfloat16* __restrict__ Bhi, const __nv_bfloat16* __restrict__ Blo,
    float* __restrict__ C, int N, int K)
{
    extern __shared__ __align__(1024) char gsm[];
    const uint32_t sbase = smem_u32(gsm);
    const int tid = threadIdx.x;
    const int wid = tid >> 5;
    const int lane = tid & 31;
    const int m0 = blockIdx.y * 128;
    const int n0 = blockIdx.x * 128;
    const int NK = K >> 5;                // 32-wide K chunks

    const int wm = (wid & 1) * 64;        // warp m offset in tile
    const int wn = (wid >> 1) * 32;       // warp n offset in tile

    auto load_chunk = [&](int ko, int s) {
        const uint32_t stg = sbase + s * GSTAGE_BYTES;
        const int k0 = ko * 32;
#pragma unroll
        for (int it = 0; it < 8; it++) {
            int flat = tid + it * 256;        // 0..2047
            int tile = flat >> 9;             // 0..3
            int within = flat & 511;
            int row = within >> 2;            // 0..127
            int c = within & 3;               // 16B chunk
            const __nv_bfloat16* gp;
            if (tile == 0)      gp = Ahi + (long)(m0 + row) * K + k0 + c * 8;
            else if (tile == 1) gp = Alo + (long)(m0 + row) * K + k0 + c * 8;
            else if (tile == 2) gp = Bhi + (long)(n0 + row) * K + k0 + c * 8;
            else                gp = Blo + (long)(n0 + row) * K + k0 + c * 8;
            cp16(stg + tile * TILE_B + swz(row, c), gp);
        }
        cpcommit();
    };

    const int npre = (NK < GSTAGES) ? NK : GSTAGES;
    for (int k = 0; k < npre; k++) load_chunk(k, k);

    float acc[4][4][4];
#pragma unroll
    for (int i = 0; i < 4; i++)
#pragma unroll
        for (int j = 0; j < 4; j++)
#pragma unroll
            for (int q = 0; q < 4; q++) acc[i][j][q] = 0.0f;

    const int a_row_off = ((lane >> 3) & 1) * 8 + (lane & 7);
    const int a_k_off = (lane >> 4);
    const int b_row = wn + lane;

    for (int k = 0; k < NK; k++) {
        const int s = k % GSTAGES;
        const int rem = NK - 1 - k;
        if (rem >= GSTAGES - 1)      cpwait<GSTAGES - 1>();
        else if (rem == 1)           cpwait<1>();
        else                         cpwait<0>();
        __syncthreads();

        const uint32_t stg = sbase + s * GSTAGE_BYTES;
        const uint32_t ah = stg;
        const uint32_t al = stg + TILE_B;
        const uint32_t bh = stg + 2 * TILE_B;
        const uint32_t bl = stg + 3 * TILE_B;

#pragma unroll
        for (int ks = 0; ks < 2; ks++) {
            const int kc = ks * 2;
            uint32_t Ah[4][4], Al[4][4];
            uint32_t Bh0[4], Bh1[4], Bl0[4], Bl1[4];
#pragma unroll
            for (int mt = 0; mt < 4; mt++) {
                const int r = wm + mt * 16 + a_row_off;
                ldsm4(Ah[mt], ah + swz(r, kc + a_k_off));
                ldsm4(Al[mt], al + swz(r, kc + a_k_off));
            }
            ldsm4(Bh0, bh + swz(b_row, kc));
            ldsm4(Bh1, bh + swz(b_row, kc + 1));
            ldsm4(Bl0, bl + swz(b_row, kc));
            ldsm4(Bl1, bl + swz(b_row, kc + 1));
#pragma unroll
            for (int mt = 0; mt < 4; mt++) {
#pragma unroll
                for (int nt = 0; nt < 4; nt++) {
                    mma_bf16(acc[mt][nt], Ah[mt], Bh0[nt], Bh1[nt]);
                    mma_bf16(acc[mt][nt], Ah[mt], Bl0[nt], Bl1[nt]);
                    mma_bf16(acc[mt][nt], Al[mt], Bh0[nt], Bh1[nt]);
                }
            }
        }
        __syncthreads();
        if (k + GSTAGES < NK) load_chunk(k + GSTAGES, s);
    }

#pragma unroll
    for (int mt = 0; mt < 4; mt++) {
#pragma unroll
        for (int nt = 0; nt < 4; nt++) {
            const int row = m0 + wm + mt * 16 + (lane >> 2);
            const int col = n0 + wn + nt * 8 + (lane & 3) * 2;
            float2 v0 = make_float2(acc[mt][nt][0], acc[mt][nt][1]);
            float2 v1 = make_float2(acc[mt][nt][2], acc[mt][nt][3]);
            *(float2*)&C[(long)row * N + col] = v0;
            *(float2*)&C[(long)(row + 8) * N + col] = v1;
        }
    }
}

// ---------------------------------------------------------------------------
// Persistent LSTM recurrence: all 16 steps in one kernel, grid barrier/step.
// RGRID=256 blocks of 256 threads. Block (bt, jt) owns batch tile b0..b0+15,
// hidden tile j0..j0+JT-1 (all 4 gates). JT = H/32 (8 for H=256, 16 for 512).
// Per step: smem-cache h-tile (transposed), K-loop FMA, smem gate exchange,
// c/h update, ping-pong h write, grid barrier.
// ---------------------------------------------------------------------------
template <int H, bool WRITE_BF16>
__global__ __launch_bounds__(256) void lstm_persistent(
    const float* __restrict__ pre,     // [T][128][4H]
    const float* __restrict__ Whh,     // [4H][H]
    const float* __restrict__ bias,    // [4H]
    float* __restrict__ hbuf,          // [2][128][H], buf 0 zeroed
    float* __restrict__ cbuf,          // [128][H] zeroed
    float* __restrict__ yout,          // [T][128][H] (layer2) or unused
    __nv_bfloat16* __restrict__ yhi,   // layer1 bf16 hi [T*128][H]
    __nv_bfloat16* __restrict__ ylo)   // layer1 bf16 lo
{
    constexpr int JT = H / 32;         // hidden cols per block
    constexpr int NC = (JT * 4) / 16;  // (j,g) combos per thread
    constexpr int K = H;
    constexpr int K4 = K / 4;
    constexpr int JSH = (JT == 8) ? 3 : 4;   // log2(JT)

    __shared__ float sh[16 * K];       // transposed h tile: sh[k*16 + bb]
    __shared__ float sx[4 * JT * 16];  // gate exchange: sx[cq*16 + bb]

    const int tid = threadIdx.x;
    const int bl = tid & 15;           // local batch row
    const int q = tid >> 4;            // combo group 0..15
    const int bx = blockIdx.x;
    const int b0 = (bx & 7) * 16;
    const int j0 = (bx >> 3) * JT;

    const unsigned gen0 = *(volatile unsigned*)&g_bar_gen;

    // weight row pointers (fixed over steps)
    const float* wr[NC];
#pragma unroll
    for (int p = 0; p < NC; p++) {
        const int cq = q + 16 * p;
        const int j = j0 + (cq & (JT - 1));
        const int g = cq >> JSH;
        wr[p] = Whh + (long)(g * H + j) * K;
    }

    for (int t = 0; t < T_STEPS; t++) {
        const float* hin = hbuf + (t & 1) * (128 * H);
        float* hnext = hbuf + ((t + 1) & 1) * (128 * H);

        // load h tile, transposed into smem
        for (int idx = tid; idx < 16 * K4; idx += 256) {
            const int bb = idx / K4;
            const int k4 = idx - bb * K4;
            float4 v = ((const float4*)(hin + (b0 + bb) * K))[k4];
            float* d = &sh[(k4 * 4) * 16 + bb];
            d[0]  = v.x;
            d[16] = v.y;
            d[32] = v.z;
            d[48] = v.w;
        }
        __syncthreads();

        float acc[NC];
#pragma unroll
        for (int p = 0; p < NC; p++) acc[p] = 0.0f;

#pragma unroll 4
        for (int k = 0; k < K; k += 4) {
            const float h0 = sh[(k + 0) * 16 + bl];
            const float h1 = sh[(k + 1) * 16 + bl];
            const float h2 = sh[(k + 2) * 16 + bl];
            const float h3 = sh[(k + 3) * 16 + bl];
#pragma unroll
            for (int p = 0; p < NC; p++) {
                float4 w = *(const float4*)(wr[p] + k);
                acc[p] = fmaf(h0, w.x, acc[p]);
                acc[p] = fmaf(h1, w.y, acc[p]);
                acc[p] = fmaf(h2, w.z, acc[p]);
                acc[p] = fmaf(h3, w.w, acc[p]);
            }
        }

        // exchange gates through smem
#pragma unroll
        for (int p = 0; p < NC; p++)
            sx[(q + 16 * p) * 16 + bl] = acc[p];
        __syncthreads();

        // update: one thread per (b, j)
        if (tid < 16 * JT) {
            const int ub = tid & 15;
            const int uj = tid >> 4;
            const int b = b0 + ub;
            const int jj = j0 + uj;
            const float* pt = pre + ((long)t * 128 + b) * (4 * H);

            const float gi = sx[(0 * JT + uj) * 16 + ub] + pt[0 * H + jj] + bias[0 * H + jj];
            const float gf = sx[(1 * JT + uj) * 16 + ub] + pt[1 * H + jj] + bias[1 * H + jj];
            const float gg = sx[(2 * JT + uj) * 16 + ub] + pt[2 * H + jj] + bias[2 * H + jj];
            const float go = sx[(3 * JT + uj) * 16 + ub] + pt[3 * H + jj] + bias[3 * H + jj];

            const float cold = cbuf[b * H + jj];
            const float cn = sigmoidf_(gf) * cold + sigmoidf_(gi) * tanhf(gg);
            const float hn = sigmoidf_(go) * tanhf(cn);

            cbuf[b * H + jj] = cn;
            hnext[b * H + jj] = hn;
            if (WRITE_BF16) {
                const long oi = ((long)t * 128 + b) * H + jj;
                __nv_bfloat16 hv = __float2bfloat16(hn);
                yhi[oi] = hv;
                ylo[oi] = __float2bfloat16(hn - __bfloat162float(hv));
            } else {
                yout[((long)t * 128 + b) * H + jj] = hn;
            }
        }

        if (t < T_STEPS - 1) {
            grid_barrier(gen0 + (unsigned)(t + 1));
        }
    }
}

// ---------------------------------------------------------------------------
extern "C" void kernel_launch(void* const* d_in, const int* in_sizes, int n_in,
                              void* d_out, int out_size)
{
    const float* inp  = (const float*)d_in[0];   // [128,16,12288] flat [2048,12288]
    const float* Wih1 = (const float*)d_in[1];   // [1024,12288]
    const float* Whh1 = (const float*)d_in[2];   // [1024,256]
    const float* b1   = (const float*)d_in[3];   // [1024]
    const float* Wih2 = (const float*)d_in[4];   // [2048,256]
    const float* Whh2 = (const float*)d_in[5];   // [2048,512]
    const float* b2   = (const float*)d_in[6];   // [2048]
    float* out = (float*)d_out;                  // [16,128,512] flat

    __nv_bfloat16 *Xhi, *Xlo, *W1hi, *W1lo, *W2hi, *W2lo, *y1hi, *y1lo;
    float *pre1, *pre2, *h1, *c1, *h2, *c2;
    cudaGetSymbolAddress((void**)&Xhi,  g_Xhi);
    cudaGetSymbolAddress((void**)&Xlo,  g_Xlo);
    cudaGetSymbolAddress((void**)&W1hi, g_W1hi);
    cudaGetSymbolAddress((void**)&W1lo, g_W1lo);
    cudaGetSymbolAddress((void**)&W2hi, g_W2hi);
    cudaGetSymbolAddress((void**)&W2lo, g_W2lo);
    cudaGetSymbolAddress((void**)&y1hi, g_y1hi);
    cudaGetSymbolAddress((void**)&y1lo, g_y1lo);
    cudaGetSymbolAddress((void**)&pre1, g_pre1);
    cudaGetSymbolAddress((void**)&pre2, g_pre2);
    cudaGetSymbolAddress((void**)&h1, g_h1);
    cudaGetSymbolAddress((void**)&c1, g_c1);
    cudaGetSymbolAddress((void**)&h2, g_h2);
    cudaGetSymbolAddress((void**)&c2, g_c2);

    cudaFuncSetAttribute(gemm_bf16split,
                         cudaFuncAttributeMaxDynamicSharedMemorySize, GSMEM_TOTAL);

    // 0) fresh recurrent state
    zero_states_kernel<<<256, 256>>>();

    // 1) bf16 hi/lo splits of X, W1, W2
    split_kernel<<<(2048 * 12288 / 4 + 255) / 256, 256>>>(inp,  Xhi,  Xlo,  2048 * 12288 / 4);
    split_kernel<<<(1024 * 12288 / 4 + 255) / 256, 256>>>(Wih1, W1hi, W1lo, 1024 * 12288 / 4);
    split_kernel<<<(2048 * 256 / 4 + 255) / 256, 256>>>(Wih2, W2hi, W2lo, 2048 * 256 / 4);

    // 2) layer-1 input projection (HMMA): pre1[2048,1024]
    gemm_bf16split<<<dim3(1024 / 128, 2048 / 128), 256, GSMEM_TOTAL>>>(
        Xhi, Xlo, W1hi, W1lo, pre1, 1024, IN_DIM);

    // 3) layer-1 recurrence: ONE persistent kernel, 16 steps internal
    lstm_persistent<H1_DIM, true><<<RGRID, 256>>>(
        pre1, Whh1, b1, h1, c1, nullptr, y1hi, y1lo);

    // 4) layer-2 input projection (HMMA): pre2[2048,2048]
    gemm_bf16split<<<dim3(2048 / 128, 2048 / 128), 256, GSMEM_TOTAL>>>(
        y1hi, y1lo, W2hi, W2lo, pre2, 2048, H1_DIM);

    // 5) layer-2 recurrence: ONE persistent kernel -> d_out
    lstm_persistent<H2_DIM, false><<<RGRID, 256>>>(
        pre2, Whh2, b2, h2, c2, out, nullptr, nullptr);
}

// round 8
// speedup vs baseline: 1.7147x; 1.7147x over previous
#include <cuda_runtime.h>
#include <cuda_bf16.h>
#include <math.h>
#include <stdint.h>

// Problem constants
#define T_STEPS 16
#define BATCH   128
#define IN_DIM  12288
#define H1_DIM  256
#define H2_DIM  512

// ---------------------------------------------------------------------------
// Device-global scratch (no allocation allowed)
// ---------------------------------------------------------------------------
__device__ __align__(256) __nv_bfloat16 g_Xhi [2048 * 12288];
__device__ __align__(256) __nv_bfloat16 g_Xlo [2048 * 12288];
__device__ __align__(256) __nv_bfloat16 g_W1hi[1024 * 12288];
__device__ __align__(256) __nv_bfloat16 g_W1lo[1024 * 12288];
__device__ __align__(256) __nv_bfloat16 g_W2hi[2048 * 256];
__device__ __align__(256) __nv_bfloat16 g_W2lo[2048 * 256];
__device__ __align__(256) __nv_bfloat16 g_Whh1hi[1024 * 256];
__device__ __align__(256) __nv_bfloat16 g_Whh1lo[1024 * 256];
__device__ __align__(256) __nv_bfloat16 g_Whh2hi[2048 * 512];
__device__ __align__(256) __nv_bfloat16 g_Whh2lo[2048 * 512];

// h sequences incl. leading zero slice: slice s = h after step s-1 (s=0 -> zeros)
__device__ __align__(256) __nv_bfloat16 g_y1hi[17 * 128 * 256];
__device__ __align__(256) __nv_bfloat16 g_y1lo[17 * 128 * 256];
__device__ __align__(256) __nv_bfloat16 g_h2hi[17 * 128 * 512];
__device__ __align__(256) __nv_bfloat16 g_h2lo[17 * 128 * 512];

__device__ float g_pre1 [2 * 2048 * 1024];  // GEMM1 K-split partials (z=2)
__device__ float g_pre2 [2048 * 2048];      // [T*B, 4*H2]
__device__ float g_part1[8 * 128 * 1024];   // rec k-split partials layer 1
__device__ float g_part2[8 * 128 * 2048];   // rec k-split partials layer 2
__device__ float g_c1[128 * 256];
__device__ float g_c2[128 * 512];

__device__ __forceinline__ float sigmoidf_(float x) {
    return 1.0f / (1.0f + expf(-x));
}

// ---------------------------------------------------------------------------
// PTX helpers (compute_103-safe: cp.async + ldmatrix + mma.sync only)
// ---------------------------------------------------------------------------
__device__ __forceinline__ uint32_t smem_u32(const void* p) {
    uint32_t a;
    asm("{ .reg .u64 t; cvta.to.shared.u64 t, %1; cvt.u32.u64 %0, t; }"
        : "=r"(a) : "l"(p));
    return a;
}

template <int N>
__device__ __forceinline__ void cpwait() {
    asm volatile("cp.async.wait_group %0;" :: "n"(N));
}

__device__ __forceinline__ void cp16(uint32_t dst, const void* src) {
    asm volatile("cp.async.cg.shared.global [%0], [%1], 16;"
                 :: "r"(dst), "l"(src));
}

__device__ __forceinline__ void cpcommit() {
    asm volatile("cp.async.commit_group;");
}

__device__ __forceinline__ void ldsm4(uint32_t* r, uint32_t addr) {
    asm volatile("ldmatrix.sync.aligned.m8n8.x4.shared.b16 {%0,%1,%2,%3}, [%4];"
                 : "=r"(r[0]), "=r"(r[1]), "=r"(r[2]), "=r"(r[3]) : "r"(addr));
}

__device__ __forceinline__ void mma_bf16(float* d, const uint32_t* a,
                                         uint32_t b0, uint32_t b1) {
    asm volatile(
        "mma.sync.aligned.m16n8k16.row.col.f32.bf16.bf16.f32 "
        "{%0,%1,%2,%3}, {%4,%5,%6,%7}, {%8,%9}, {%0,%1,%2,%3};"
        : "+f"(d[0]), "+f"(d[1]), "+f"(d[2]), "+f"(d[3])
        : "r"(a[0]), "r"(a[1]), "r"(a[2]), "r"(a[3]), "r"(b0), "r"(b1));
}

// ---------------------------------------------------------------------------
// Zero the recurrent states (h slice 0 + c)
// ---------------------------------------------------------------------------
__global__ void zero_states_kernel() {
    int i = blockIdx.x * blockDim.x + threadIdx.x;
    if (i < 128 * 256) {
        g_y1hi[i] = __nv_bfloat16(0.0f);
        g_y1lo[i] = __nv_bfloat16(0.0f);
        g_c1[i] = 0.0f;
    }
    if (i < 128 * 512) {
        g_h2hi[i] = __nv_bfloat16(0.0f);
        g_h2lo[i] = __nv_bfloat16(0.0f);
        g_c2[i] = 0.0f;
    }
}

// ---------------------------------------------------------------------------
// fp32 -> (hi, lo) bf16 split
// ---------------------------------------------------------------------------
__global__ void split_kernel(const float* __restrict__ x,
                             __nv_bfloat16* __restrict__ hi,
                             __nv_bfloat16* __restrict__ lo, int n4) {
    int i = blockIdx.x * blockDim.x + threadIdx.x;
    if (i >= n4) return;
    float4 v = ((const float4*)x)[i];
    __nv_bfloat16 h0 = __float2bfloat16(v.x);
    __nv_bfloat16 h1 = __float2bfloat16(v.y);
    __nv_bfloat16 h2 = __float2bfloat16(v.z);
    __nv_bfloat16 h3 = __float2bfloat16(v.w);
    __nv_bfloat16 l0 = __float2bfloat16(v.x - __bfloat162float(h0));
    __nv_bfloat16 l1 = __float2bfloat16(v.y - __bfloat162float(h1));
    __nv_bfloat16 l2 = __float2bfloat16(v.z - __bfloat162float(h2));
    __nv_bfloat16 l3 = __float2bfloat16(v.w - __bfloat162float(h3));
    ((__nv_bfloat162*)hi)[i * 2 + 0] = __nv_bfloat162(h0, h1);
    ((__nv_bfloat162*)hi)[i * 2 + 1] = __nv_bfloat162(h2, h3);
    ((__nv_bfloat162*)lo)[i * 2 + 0] = __nv_bfloat162(l0, l1);
    ((__nv_bfloat162*)lo)[i * 2 + 1] = __nv_bfloat162(l2, l3);
}

// ---------------------------------------------------------------------------
// Split-bf16 HMMA GEMM with optional K-split partials:
//   C_z[m][n] = sum_{k in z-th K slice} A[m][k]*B[n][k]   (fp32)
// A = Ahi+Alo, B = Bhi+Blo; accumulates hi*hi + hi*lo + lo*hi.
// Tile 128x128, K-chunks of 32, up-to-3-stage cp.async pipeline, 256 threads.
// grid = (N/128, M/128, KZ); Ksub = K/KZ (mult of 32); ldK = row stride.
// C output for slice z at C + z*partStride.
// ---------------------------------------------------------------------------
#define GSTAGES 3
#define TILE_B 8192                       // one 128x32 bf16 tile
#define GSTAGE_BYTES (4 * TILE_B)         // Ah, Al, Bh, Bl
#define GSMEM_TOTAL (GSTAGES * GSTAGE_BYTES)

// swizzled offset of (row, chunk) within an 8KB tile; chunk = 16B = 8 bf16
__device__ __forceinline__ uint32_t swz(int row, int c) {
    return (uint32_t)(row * 64 + 16 * (c ^ ((row >> 1) & 3)));
}

__global__ __launch_bounds__(256) void gemm_bf16split(
    const __nv_bfloat16* __restrict__ Ahi, const __nv_bfloat16* __restrict__ Alo,
    const __nv_bfloat16* __restrict__ Bhi, const __nv_bfloat16* __restrict__ Blo,
    float* __restrict__ C, int N, int ldK, int Ksub, long partStride)
{
    extern __shared__ __align__(1024) char gsm[];
    const uint32_t sbase = smem_u32(gsm);
    const int tid = threadIdx.x;
    const int wid = tid >> 5;
    const int lane = tid & 31;
    const int m0 = blockIdx.y * 128;
    const int n0 = blockIdx.x * 128;
    const int koff = blockIdx.z * Ksub;
    const int NK = Ksub >> 5;             // 32-wide K chunks

    C += (long)blockIdx.z * partStride;

    const int wm = (wid & 1) * 64;        // warp m offset in tile
    const int wn = (wid >> 1) * 32;       // warp n offset in tile

    auto load_chunk = [&](int ko, int s) {
        const uint32_t stg = sbase + s * GSTAGE_BYTES;
        const int k0 = koff + ko * 32;
#pragma unroll
        for (int it = 0; it < 8; it++) {
            int flat = tid + it * 256;        // 0..2047
            int tile = flat >> 9;             // 0..3
            int within = flat & 511;
            int row = within >> 2;            // 0..127
            int c = within & 3;               // 16B chunk
            const __nv_bfloat16* gp;
            if (tile == 0)      gp = Ahi + (long)(m0 + row) * ldK + k0 + c * 8;
            else if (tile == 1) gp = Alo + (long)(m0 + row) * ldK + k0 + c * 8;
            else if (tile == 2) gp = Bhi + (long)(n0 + row) * ldK + k0 + c * 8;
            else                gp = Blo + (long)(n0 + row) * ldK + k0 + c * 8;
            cp16(stg + tile * TILE_B + swz(row, c), gp);
        }
        cpcommit();
    };

    const int npre = (NK < GSTAGES) ? NK : GSTAGES;
    for (int k = 0; k < npre; k++) load_chunk(k, k);

    float acc[4][4][4];
#pragma unroll
    for (int i = 0; i < 4; i++)
#pragma unroll
        for (int j = 0; j < 4; j++)
#pragma unroll
            for (int q = 0; q < 4; q++) acc[i][j][q] = 0.0f;

    const int a_row_off = ((lane >> 3) & 1) * 8 + (lane & 7);
    const int a_k_off = (lane >> 4);
    const int b_row = wn + lane;

    for (int k = 0; k < NK; k++) {
        const int s = k % GSTAGES;
        const int rem = NK - 1 - k;
        if (rem >= GSTAGES - 1)      cpwait<GSTAGES - 1>();
        else if (rem == 1)           cpwait<1>();
        else                         cpwait<0>();
        __syncthreads();

        const uint32_t stg = sbase + s * GSTAGE_BYTES;
        const uint32_t ah = stg;
        const uint32_t al = stg + TILE_B;
        const uint32_t bh = stg + 2 * TILE_B;
        const uint32_t bl = stg + 3 * TILE_B;

#pragma unroll
        for (int ks = 0; ks < 2; ks++) {
            const int kc = ks * 2;
            uint32_t Ah[4][4], Al[4][4];
            uint32_t Bh0[4], Bh1[4], Bl0[4], Bl1[4];
#pragma unroll
            for (int mt = 0; mt < 4; mt++) {
                const int r = wm + mt * 16 + a_row_off;
                ldsm4(Ah[mt], ah + swz(r, kc + a_k_off));
                ldsm4(Al[mt], al + swz(r, kc + a_k_off));
            }
            ldsm4(Bh0, bh + swz(b_row, kc));
            ldsm4(Bh1, bh + swz(b_row, kc + 1));
            ldsm4(Bl0, bl + swz(b_row, kc));
            ldsm4(Bl1, bl + swz(b_row, kc + 1));
#pragma unroll
            for (int mt = 0; mt < 4; mt++) {
#pragma unroll
                for (int nt = 0; nt < 4; nt++) {
                    mma_bf16(acc[mt][nt], Ah[mt], Bh0[nt], Bh1[nt]);
                    mma_bf16(acc[mt][nt], Ah[mt], Bl0[nt], Bl1[nt]);
                    mma_bf16(acc[mt][nt], Al[mt], Bh0[nt], Bh1[nt]);
                }
            }
        }
        __syncthreads();
        if (k + GSTAGES < NK) load_chunk(k + GSTAGES, s);
    }

#pragma unroll
    for (int mt = 0; mt < 4; mt++) {
#pragma unroll
        for (int nt = 0; nt < 4; nt++) {
            const int row = m0 + wm + mt * 16 + (lane >> 2);
            const int col = n0 + wn + nt * 8 + (lane & 3) * 2;
            float2 v0 = make_float2(acc[mt][nt][0], acc[mt][nt][1]);
            float2 v1 = make_float2(acc[mt][nt][2], acc[mt][nt][3]);
            *(float2*)&C[(long)row * N + col] = v0;
            *(float2*)&C[(long)(row + 8) * N + col] = v1;
        }
    }
}

// ---------------------------------------------------------------------------
// Gate kernel: sum KZ rec partials + PREZ pre slices + bias, nonlinearity,
// c/h update; h emitted as bf16 hi/lo (next-step GEMM input), optional fp32 y.
// One thread per (b, j). grid = B*H/256.
// ---------------------------------------------------------------------------
template <int H, int KZ, int PREZ, bool L2OUT>
__global__ __launch_bounds__(256) void lstm_gates2(
    const float* __restrict__ part,     // [KZ][128][4H]
    const float* __restrict__ pre,      // offset to t; slices stride = pstride
    long pstride,
    const float* __restrict__ bias,     // [4H]
    float* __restrict__ c,              // [128][H]
    __nv_bfloat16* __restrict__ hhi,    // next h slice (hi)
    __nv_bfloat16* __restrict__ hlo,    // next h slice (lo)
    float* __restrict__ out)            // fp32 y slice (layer 2) or unused
{
    const int idx = blockIdx.x * 256 + threadIdx.x;   // b*H + j
    const int b = idx / H;
    const int j = idx % H;

    float gate[4];
#pragma unroll
    for (int g = 0; g < 4; g++) {
        const int o = b * 4 * H + g * H + j;
        float v = bias[g * H + j];
#pragma unroll
        for (int z = 0; z < PREZ; z++) v += pre[(long)z * pstride + o];
#pragma unroll
        for (int z = 0; z < KZ; z++) v += part[(long)z * (128 * 4 * H) + o];
        gate[g] = v;
    }

    const float cold = c[idx];
    const float cn = sigmoidf_(gate[1]) * cold + sigmoidf_(gate[0]) * tanhf(gate[2]);
    const float hn = sigmoidf_(gate[3]) * tanhf(cn);

    c[idx] = cn;
    __nv_bfloat16 hv = __float2bfloat16(hn);
    hhi[idx] = hv;
    hlo[idx] = __float2bfloat16(hn - __bfloat162float(hv));
    if (L2OUT) out[idx] = hn;
}

// ---------------------------------------------------------------------------
extern "C" void kernel_launch(void* const* d_in, const int* in_sizes, int n_in,
                              void* d_out, int out_size)
{
    const float* inp  = (const float*)d_in[0];   // [128,16,12288] flat [2048,12288]
    const float* Wih1 = (const float*)d_in[1];   // [1024,12288]
    const float* Whh1 = (const float*)d_in[2];   // [1024,256]
    const float* b1   = (const float*)d_in[3];   // [1024]
    const float* Wih2 = (const float*)d_in[4];   // [2048,256]
    const float* Whh2 = (const float*)d_in[5];   // [2048,512]
    const float* b2   = (const float*)d_in[6];   // [2048]
    float* out = (float*)d_out;                  // [16,128,512] flat

    __nv_bfloat16 *Xhi, *Xlo, *W1hi, *W1lo, *W2hi, *W2lo;
    __nv_bfloat16 *R1hi, *R1lo, *R2hi, *R2lo, *y1hi, *y1lo, *h2hi, *h2lo;
    float *pre1, *pre2, *part1, *part2, *c1, *c2;
    cudaGetSymbolAddress((void**)&Xhi,  g_Xhi);
    cudaGetSymbolAddress((void**)&Xlo,  g_Xlo);
    cudaGetSymbolAddress((void**)&W1hi, g_W1hi);
    cudaGetSymbolAddress((void**)&W1lo, g_W1lo);
    cudaGetSymbolAddress((void**)&W2hi, g_W2hi);
    cudaGetSymbolAddress((void**)&W2lo, g_W2lo);
    cudaGetSymbolAddress((void**)&R1hi, g_Whh1hi);
    cudaGetSymbolAddress((void**)&R1lo, g_Whh1lo);
    cudaGetSymbolAddress((void**)&R2hi, g_Whh2hi);
    cudaGetSymbolAddress((void**)&R2lo, g_Whh2lo);
    cudaGetSymbolAddress((void**)&y1hi, g_y1hi);
    cudaGetSymbolAddress((void**)&y1lo, g_y1lo);
    cudaGetSymbolAddress((void**)&h2hi, g_h2hi);
    cudaGetSymbolAddress((void**)&h2lo, g_h2lo);
    cudaGetSymbolAddress((void**)&pre1, g_pre1);
    cudaGetSymbolAddress((void**)&pre2, g_pre2);
    cudaGetSymbolAddress((void**)&part1, g_part1);
    cudaGetSymbolAddress((void**)&part2, g_part2);
    cudaGetSymbolAddress((void**)&c1, g_c1);
    cudaGetSymbolAddress((void**)&c2, g_c2);

    cudaFuncSetAttribute(gemm_bf16split,
                         cudaFuncAttributeMaxDynamicSharedMemorySize, GSMEM_TOTAL);

    // 0) fresh recurrent state (h slice 0 = 0, c = 0)
    zero_states_kernel<<<256, 256>>>();

    // 1) bf16 hi/lo splits of X and all weights
    split_kernel<<<(2048 * 12288 / 4 + 255) / 256, 256>>>(inp,  Xhi,  Xlo,  2048 * 12288 / 4);
    split_kernel<<<(1024 * 12288 / 4 + 255) / 256, 256>>>(Wih1, W1hi, W1lo, 1024 * 12288 / 4);
    split_kernel<<<(2048 * 256 / 4 + 255) / 256, 256>>>(Wih2, W2hi, W2lo, 2048 * 256 / 4);
    split_kernel<<<(1024 * 256 / 4 + 255) / 256, 256>>>(Whh1, R1hi, R1lo, 1024 * 256 / 4);
    split_kernel<<<(2048 * 512 / 4 + 255) / 256, 256>>>(Whh2, R2hi, R2lo, 2048 * 512 / 4);

    // 2) layer-1 input projection (HMMA, K-split x2): pre1[2][2048,1024]
    gemm_bf16split<<<dim3(8, 16, 2), 256, GSMEM_TOTAL>>>(
        Xhi, Xlo, W1hi, W1lo, pre1, 1024, IN_DIM, IN_DIM / 2,
        (long)2048 * 1024);

    // 3) layer-1 recurrence: per step, HMMA k-split partial GEMM + gates
    for (int t = 0; t < T_STEPS; t++) {
        gemm_bf16split<<<dim3(8, 1, 8), 256, GSMEM_TOTAL>>>(
            y1hi + (long)t * 128 * H1_DIM, y1lo + (long)t * 128 * H1_DIM,
            R1hi, R1lo, part1, 4 * H1_DIM, H1_DIM, H1_DIM / 8,
            (long)128 * 4 * H1_DIM);
        lstm_gates2<H1_DIM, 8, 2, false><<<BATCH * H1_DIM / 256, 256>>>(
            part1, pre1 + (long)t * 128 * 4 * H1_DIM, (long)2048 * 1024,
            b1, c1,
            y1hi + (long)(t + 1) * 128 * H1_DIM,
            y1lo + (long)(t + 1) * 128 * H1_DIM,
            nullptr);
    }

    // 4) layer-2 input projection (HMMA): pre2[2048,2048]; A = y1 slices 1..16
    gemm_bf16split<<<dim3(16, 16, 1), 256, GSMEM_TOTAL>>>(
        y1hi + 128 * H1_DIM, y1lo + 128 * H1_DIM,
        W2hi, W2lo, pre2, 2048, H1_DIM, H1_DIM, 0);

    // 5) layer-2 recurrence -> d_out
    for (int t = 0; t < T_STEPS; t++) {
        gemm_bf16split<<<dim3(16, 1, 8), 256, GSMEM_TOTAL>>>(
            h2hi + (long)t * 128 * H2_DIM, h2lo + (long)t * 128 * H2_DIM,
            R2hi, R2lo, part2, 4 * H2_DIM, H2_DIM, H2_DIM / 8,
            (long)128 * 4 * H2_DIM);
        lstm_gates2<H2_DIM, 8, 1, true><<<BATCH * H2_DIM / 256, 256>>>(
            part2, pre2 + (long)t * 128 * 4 * H2_DIM, 0,
            b2, c2,
            h2hi + (long)(t + 1) * 128 * H2_DIM,
            h2lo + (long)(t + 1) * 128 * H2_DIM,
            out + (long)t * 128 * H2_DIM);
    }
}

// round 9
// speedup vs baseline: 2.1187x; 1.2356x over previous
#include <cuda_runtime.h>
#include <cuda_bf16.h>
#include <cuda_fp16.h>
#include <math.h>
#include <stdint.h>

// Problem constants
#define T_STEPS 16
#define BATCH   128
#define IN_DIM  12288
#define H1_DIM  256
#define H2_DIM  512

// ---------------------------------------------------------------------------
// Device-global scratch (no allocation allowed)
// ---------------------------------------------------------------------------
__device__ __align__(256) __half g_Xhi [2048 * 12288];
__device__ __align__(256) __half g_Xlo [2048 * 12288];
__device__ __align__(256) __half g_W1h [1024 * 12288];

__device__ __align__(256) __nv_bfloat16 g_W2hi[2048 * 256];
__device__ __align__(256) __nv_bfloat16 g_W2lo[2048 * 256];
__device__ __align__(256) __nv_bfloat16 g_Whh1hi[1024 * 256];
__device__ __align__(256) __nv_bfloat16 g_Whh1lo[1024 * 256];
__device__ __align__(256) __nv_bfloat16 g_Whh2hi[2048 * 512];
__device__ __align__(256) __nv_bfloat16 g_Whh2lo[2048 * 512];

// h sequences incl. leading zero slice: slice s = h after step s-1 (s=0 -> zeros)
__device__ __align__(256) __nv_bfloat16 g_y1hi[17 * 128 * 256];
__device__ __align__(256) __nv_bfloat16 g_y1lo[17 * 128 * 256];
__device__ __align__(256) __nv_bfloat16 g_h2hi[17 * 128 * 512];
__device__ __align__(256) __nv_bfloat16 g_h2lo[17 * 128 * 512];

__device__ float g_pre1 [2 * 2048 * 1024];  // GEMM1 K-split partials (z=2)
__device__ float g_pre2 [2048 * 2048];      // [T*B, 4*H2]
__device__ float g_part1[8 * 128 * 1024];   // rec k-split partials layer 1
__device__ float g_part2[8 * 128 * 2048];   // rec k-split partials layer 2
__device__ float g_c1[128 * 256];
__device__ float g_c2[128 * 512];

__device__ __forceinline__ float sigmoidf_(float x) {
    return 1.0f / (1.0f + expf(-x));
}

// ---------------------------------------------------------------------------
// PTX helpers (compute_103-safe: cp.async + ldmatrix + mma.sync only)
// ---------------------------------------------------------------------------
__device__ __forceinline__ uint32_t smem_u32(const void* p) {
    uint32_t a;
    asm("{ .reg .u64 t; cvta.to.shared.u64 t, %1; cvt.u32.u64 %0, t; }"
        : "=r"(a) : "l"(p));
    return a;
}

template <int N>
__device__ __forceinline__ void cpwait() {
    asm volatile("cp.async.wait_group %0;" :: "n"(N));
}

__device__ __forceinline__ void cp16(uint32_t dst, const void* src) {
    asm volatile("cp.async.cg.shared.global [%0], [%1], 16;"
                 :: "r"(dst), "l"(src));
}

__device__ __forceinline__ void cpcommit() {
    asm volatile("cp.async.commit_group;");
}

__device__ __forceinline__ void ldsm4(uint32_t* r, uint32_t addr) {
    asm volatile("ldmatrix.sync.aligned.m8n8.x4.shared.b16 {%0,%1,%2,%3}, [%4];"
                 : "=r"(r[0]), "=r"(r[1]), "=r"(r[2]), "=r"(r[3]) : "r"(addr));
}

__device__ __forceinline__ void mma_bf16(float* d, const uint32_t* a,
                                         uint32_t b0, uint32_t b1) {
    asm("mma.sync.aligned.m16n8k16.row.col.f32.bf16.bf16.f32 "
        "{%0,%1,%2,%3}, {%4,%5,%6,%7}, {%8,%9}, {%0,%1,%2,%3};"
        : "+f"(d[0]), "+f"(d[1]), "+f"(d[2]), "+f"(d[3])
        : "r"(a[0]), "r"(a[1]), "r"(a[2]), "r"(a[3]), "r"(b0), "r"(b1));
}

__device__ __forceinline__ void mma_f16(float* d, const uint32_t* a,
                                        uint32_t b0, uint32_t b1) {
    asm("mma.sync.aligned.m16n8k16.row.col.f32.f16.f16.f32 "
        "{%0,%1,%2,%3}, {%4,%5,%6,%7}, {%8,%9}, {%0,%1,%2,%3};"
        : "+f"(d[0]), "+f"(d[1]), "+f"(d[2]), "+f"(d[3])
        : "r"(a[0]), "r"(a[1]), "r"(a[2]), "r"(a[3]), "r"(b0), "r"(b1));
}

// ---------------------------------------------------------------------------
// Zero the recurrent states (h slice 0 + c)
// ---------------------------------------------------------------------------
__global__ void zero_states_kernel() {
    int i = blockIdx.x * blockDim.x + threadIdx.x;
    if (i < 128 * 256) {
        g_y1hi[i] = __nv_bfloat16(0.0f);
        g_y1lo[i] = __nv_bfloat16(0.0f);
        g_c1[i] = 0.0f;
    }
    if (i < 128 * 512) {
        g_h2hi[i] = __nv_bfloat16(0.0f);
        g_h2lo[i] = __nv_bfloat16(0.0f);
        g_c2[i] = 0.0f;
    }
}

// ---------------------------------------------------------------------------
// fp32 -> (hi, lo) bf16 split
// ---------------------------------------------------------------------------
__global__ void split_kernel(const float* __restrict__ x,
                             __nv_bfloat16* __restrict__ hi,
                             __nv_bfloat16* __restrict__ lo, int n4) {
    int i = blockIdx.x * blockDim.x + threadIdx.x;
    if (i >= n4) return;
    float4 v = ((const float4*)x)[i];
    __nv_bfloat16 h0 = __float2bfloat16(v.x);
    __nv_bfloat16 h1 = __float2bfloat16(v.y);
    __nv_bfloat16 h2 = __float2bfloat16(v.z);
    __nv_bfloat16 h3 = __float2bfloat16(v.w);
    __nv_bfloat16 l0 = __float2bfloat16(v.x - __bfloat162float(h0));
    __nv_bfloat16 l1 = __float2bfloat16(v.y - __bfloat162float(h1));
    __nv_bfloat16 l2 = __float2bfloat16(v.z - __bfloat162float(h2));
    __nv_bfloat16 l3 = __float2bfloat16(v.w - __bfloat162float(h3));
    ((__nv_bfloat162*)hi)[i * 2 + 0] = __nv_bfloat162(h0, h1);
    ((__nv_bfloat162*)hi)[i * 2 + 1] = __nv_bfloat162(h2, h3);
    ((__nv_bfloat162*)lo)[i * 2 + 0] = __nv_bfloat162(l0, l1);
    ((__nv_bfloat162*)lo)[i * 2 + 1] = __nv_bfloat162(l2, l3);
}

// ---------------------------------------------------------------------------
// fp32 -> (hi, lo) fp16 split   (exact to ~2^-22)
// ---------------------------------------------------------------------------
__global__ void split_f16_kernel(const float* __restrict__ x,
                                 __half* __restrict__ hi,
                                 __half* __restrict__ lo, int n4) {
    int i = blockIdx.x * blockDim.x + threadIdx.x;
    if (i >= n4) return;
    float4 v = ((const float4*)x)[i];
    __half h0 = __float2half(v.x);
    __half h1 = __float2half(v.y);
    __half h2 = __float2half(v.z);
    __half h3 = __float2half(v.w);
    __half l0 = __float2half(v.x - __half2float(h0));
    __half l1 = __float2half(v.y - __half2float(h1));
    __half l2 = __float2half(v.z - __half2float(h2));
    __half l3 = __float2half(v.w - __half2float(h3));
    ((__half2*)hi)[i * 2 + 0] = __halves2half2(h0, h1);
    ((__half2*)hi)[i * 2 + 1] = __halves2half2(h2, h3);
    ((__half2*)lo)[i * 2 + 0] = __halves2half2(l0, l1);
    ((__half2*)lo)[i * 2 + 1] = __halves2half2(l2, l3);
}

// fp32 -> fp16 quantize (hi only)
__global__ void quant_f16_kernel(const float* __restrict__ x,
                                 __half* __restrict__ hi, int n4) {
    int i = blockIdx.x * blockDim.x + threadIdx.x;
    if (i >= n4) return;
    float4 v = ((const float4*)x)[i];
    ((__half2*)hi)[i * 2 + 0] = __halves2half2(__float2half(v.x), __float2half(v.y));
    ((__half2*)hi)[i * 2 + 1] = __halves2half2(__float2half(v.z), __float2half(v.w));
}

// ---------------------------------------------------------------------------
// Shared GEMM geometry
// ---------------------------------------------------------------------------
#define GSTAGES 3
#define TILE_B 8192                       // one 128x32 x 16-bit tile
// bf16 3-term kernel: 4 tiles/stage
#define GSTAGE_BYTES (4 * TILE_B)
#define GSMEM_TOTAL (GSTAGES * GSTAGE_BYTES)
// f16 2-term kernel: 3 tiles/stage
#define FSTAGE_BYTES (3 * TILE_B)
#define FSMEM_TOTAL (GSTAGES * FSTAGE_BYTES)

// swizzled offset of (row, chunk) within an 8KB tile; chunk = 16B = 8 elems
__device__ __forceinline__ uint32_t swz(int row, int c) {
    return (uint32_t)(row * 64 + 16 * (c ^ ((row >> 1) & 3)));
}

// ---------------------------------------------------------------------------
// Split-bf16 HMMA GEMM (3 terms) with optional K-split partials.
// grid = (N/128, M/128, KZ); Ksub = K/KZ (mult of 32); ldK = row stride.
// ---------------------------------------------------------------------------
__global__ __launch_bounds__(256) void gemm_bf16split(
    const __nv_bfloat16* __restrict__ Ahi, const __nv_bfloat16* __restrict__ Alo,
    const __nv_bfloat16* __restrict__ Bhi, const __nv_bfloat16* __restrict__ Blo,
    float* __restrict__ C, int N, int ldK, int Ksub, long partStride)
{
    extern __shared__ __align__(1024) char gsm[];
    const uint32_t sbase = smem_u32(gsm);
    const int tid = threadIdx.x;
    const int wid = tid >> 5;
    const int lane = tid & 31;
    const int m0 = blockIdx.y * 128;
    const int n0 = blockIdx.x * 128;
    const int koff = blockIdx.z * Ksub;
    const int NK = Ksub >> 5;

    C += (long)blockIdx.z * partStride;

    const int wm = (wid & 1) * 64;
    const int wn = (wid >> 1) * 32;

    auto load_chunk = [&](int ko, int s) {
        const uint32_t stg = sbase + s * GSTAGE_BYTES;
        const int k0 = koff + ko * 32;
#pragma unroll
        for (int it = 0; it < 8; it++) {
            int flat = tid + it * 256;
            int tile = flat >> 9;
            int within = flat & 511;
            int row = within >> 2;
            int c = within & 3;
            const __nv_bfloat16* gp;
            if (tile == 0)      gp = Ahi + (long)(m0 + row) * ldK + k0 + c * 8;
            else if (tile == 1) gp = Alo + (long)(m0 + row) * ldK + k0 + c * 8;
            else if (tile == 2) gp = Bhi + (long)(n0 + row) * ldK + k0 + c * 8;
            else                gp = Blo + (long)(n0 + row) * ldK + k0 + c * 8;
            cp16(stg + tile * TILE_B + swz(row, c), gp);
        }
        cpcommit();
    };

    const int npre = (NK < GSTAGES) ? NK : GSTAGES;
    for (int k = 0; k < npre; k++) load_chunk(k, k);

    float acc[4][4][4];
#pragma unroll
    for (int i = 0; i < 4; i++)
#pragma unroll
        for (int j = 0; j < 4; j++)
#pragma unroll
            for (int q = 0; q < 4; q++) acc[i][j][q] = 0.0f;

    const int a_row_off = ((lane >> 3) & 1) * 8 + (lane & 7);
    const int a_k_off = (lane >> 4);
    const int b_row = wn + lane;

    for (int k = 0; k < NK; k++) {
        const int s = k % GSTAGES;
        const int rem = NK - 1 - k;
        if (rem >= GSTAGES - 1)      cpwait<GSTAGES - 1>();
        else if (rem == 1)           cpwait<1>();
        else                         cpwait<0>();
        __syncthreads();

        const uint32_t stg = sbase + s * GSTAGE_BYTES;
        const uint32_t ah = stg;
        const uint32_t al = stg + TILE_B;
        const uint32_t bh = stg + 2 * TILE_B;
        const uint32_t bl = stg + 3 * TILE_B;

#pragma unroll
        for (int ks = 0; ks < 2; ks++) {
            const int kc = ks * 2;
            uint32_t Ah[4][4], Al[4][4];
            uint32_t Bh0[4], Bh1[4], Bl0[4], Bl1[4];
#pragma unroll
            for (int mt = 0; mt < 4; mt++) {
                const int r = wm + mt * 16 + a_row_off;
                ldsm4(Ah[mt], ah + swz(r, kc + a_k_off));
                ldsm4(Al[mt], al + swz(r, kc + a_k_off));
            }
            ldsm4(Bh0, bh + swz(b_row, kc));
            ldsm4(Bh1, bh + swz(b_row, kc + 1));
            ldsm4(Bl0, bl + swz(b_row, kc));
            ldsm4(Bl1, bl + swz(b_row, kc + 1));
            // term-outermost: 16 independent accumulators between RAW reuse
#pragma unroll
            for (int mt = 0; mt < 4; mt++)
#pragma unroll
                for (int nt = 0; nt < 4; nt++)
                    mma_bf16(acc[mt][nt], Ah[mt], Bh0[nt], Bh1[nt]);
#pragma unroll
            for (int mt = 0; mt < 4; mt++)
#pragma unroll
                for (int nt = 0; nt < 4; nt++)
                    mma_bf16(acc[mt][nt], Ah[mt], Bl0[nt], Bl1[nt]);
#pragma unroll
            for (int mt = 0; mt < 4; mt++)
#pragma unroll
                for (int nt = 0; nt < 4; nt++)
                    mma_bf16(acc[mt][nt], Al[mt], Bh0[nt], Bh1[nt]);
        }
        __syncthreads();
        if (k + GSTAGES < NK) load_chunk(k + GSTAGES, s);
    }

#pragma unroll
    for (int mt = 0; mt < 4; mt++) {
#pragma unroll
        for (int nt = 0; nt < 4; nt++) {
            const int row = m0 + wm + mt * 16 + (lane >> 2);
            const int col = n0 + wn + nt * 8 + (lane & 3) * 2;
            float2 v0 = make_float2(acc[mt][nt][0], acc[mt][nt][1]);
            float2 v1 = make_float2(acc[mt][nt][2], acc[mt][nt][3]);
            *(float2*)&C[(long)row * N + col] = v0;
            *(float2*)&C[(long)(row + 8) * N + col] = v1;
        }
    }
}

// ---------------------------------------------------------------------------
// fp16 2-term GEMM: C = (Ahi + Alo) * Bh^T   == A_fp32 x fp16(B), fp32 accum.
// Same tiling; 3 smem tiles per stage. grid = (N/128, M/128, KZ).
// ---------------------------------------------------------------------------
__global__ __launch_bounds__(256) void gemm_f16_2term(
    const __half* __restrict__ Ahi, const __half* __restrict__ Alo,
    const __half* __restrict__ Bh,
    float* __restrict__ C, int N, int ldK, int Ksub, long partStride)
{
    extern __shared__ __align__(1024) char gsm[];
    const uint32_t sbase = smem_u32(gsm);
    const int tid = threadIdx.x;
    const int wid = tid >> 5;
    const int lane = tid & 31;
    const int m0 = blockIdx.y * 128;
    const int n0 = blockIdx.x * 128;
    const int koff = blockIdx.z * Ksub;
    const int NK = Ksub >> 5;

    C += (long)blockIdx.z * partStride;

    const int wm = (wid & 1) * 64;
    const int wn = (wid >> 1) * 32;

    auto load_chunk = [&](int ko, int s) {
        const uint32_t stg = sbase + s * FSTAGE_BYTES;
        const int k0 = koff + ko * 32;
#pragma unroll
        for (int it = 0; it < 6; it++) {
            int flat = tid + it * 256;        // 0..1535
            int tile = flat >> 9;             // 0..2
            int within = flat & 511;
            int row = within >> 2;
            int c = within & 3;
            const __half* gp;
            if (tile == 0)      gp = Ahi + (long)(m0 + row) * ldK + k0 + c * 8;
            else if (tile == 1) gp = Alo + (long)(m0 + row) * ldK + k0 + c * 8;
            else                gp = Bh + (long)(n0 + row) * ldK + k0 + c * 8;
            cp16(stg + tile * TILE_B + swz(row, c), gp);
        }
        cpcommit();
    };

    const int npre = (NK < GSTAGES) ? NK : GSTAGES;
    for (int k = 0; k < npre; k++) load_chunk(k, k);

    float acc[4][4][4];
#pragma unroll
    for (int i = 0; i < 4; i++)
#pragma unroll
        for (int j = 0; j < 4; j++)
#pragma unroll
            for (int q = 0; q < 4; q++) acc[i][j][q] = 0.0f;

    const int a_row_off = ((lane >> 3) & 1) * 8 + (lane & 7);
    const int a_k_off = (lane >> 4);
    const int b_row = wn + lane;

    for (int k = 0; k < NK; k++) {
        const int s = k % GSTAGES;
        const int rem = NK - 1 - k;
        if (rem >= GSTAGES - 1)      cpwait<GSTAGES - 1>();
        else if (rem == 1)           cpwait<1>();
        else                         cpwait<0>();
        __syncthreads();

        const uint32_t stg = sbase + s * FSTAGE_BYTES;
        const uint32_t ah = stg;
        const uint32_t al = stg + TILE_B;
        const uint32_t bh = stg + 2 * TILE_B;

#pragma unroll
        for (int ks = 0; ks < 2; ks++) {
            const int kc = ks * 2;
            uint32_t Ah[4][4], Al[4][4];
            uint32_t Bh0[4], Bh1[4];
#pragma unroll
            for (int mt = 0; mt < 4; mt++) {
                const int r = wm + mt * 16 + a_row_off;
                ldsm4(Ah[mt], ah + swz(r, kc + a_k_off));
                ldsm4(Al[mt], al + swz(r, kc + a_k_off));
            }
            ldsm4(Bh0, bh + swz(b_row, kc));
            ldsm4(Bh1, bh + swz(b_row, kc + 1));
#pragma unroll
            for (int mt = 0; mt < 4; mt++)
#pragma unroll
                for (int nt = 0; nt < 4; nt++)
                    mma_f16(acc[mt][nt], Ah[mt], Bh0[nt], Bh1[nt]);
#pragma unroll
            for (int mt = 0; mt < 4; mt++)
#pragma unroll
                for (int nt = 0; nt < 4; nt++)
                    mma_f16(acc[mt][nt], Al[mt], Bh0[nt], Bh1[nt]);
        }
        __syncthreads();
        if (k + GSTAGES < NK) load_chunk(k + GSTAGES, s);
    }

#pragma unroll
    for (int mt = 0; mt < 4; mt++) {
#pragma unroll
        for (int nt = 0; nt < 4; nt++) {
            const int row = m0 + wm + mt * 16 + (lane >> 2);
            const int col = n0 + wn + nt * 8 + (lane & 3) * 2;
            float2 v0 = make_float2(acc[mt][nt][0], acc[mt][nt][1]);
            float2 v1 = make_float2(acc[mt][nt][2], acc[mt][nt][3]);
            *(float2*)&C[(long)row * N + col] = v0;
            *(float2*)&C[(long)(row + 8) * N + col] = v1;
        }
    }
}

// ---------------------------------------------------------------------------
// Gate kernel: sum KZ rec partials + PREZ pre slices + bias, nonlinearity,
// c/h update; h emitted as bf16 hi/lo (next-step GEMM input), optional fp32 y.
// ---------------------------------------------------------------------------
template <int H, int KZ, int PREZ, bool L2OUT>
__global__ __launch_bounds__(256) void lstm_gates2(
    const float* __restrict__ part,     // [KZ][128][4H]
    const float* __restrict__ pre,      // offset to t; slices stride = pstride
    long pstride,
    const float* __restrict__ bias,     // [4H]
    float* __restrict__ c,              // [128][H]
    __nv_bfloat16* __restrict__ hhi,    // next h slice (hi)
    __nv_bfloat16* __restrict__ hlo,    // next h slice (lo)
    float* __restrict__ out)            // fp32 y slice (layer 2) or unused
{
    const int idx = blockIdx.x * 256 + threadIdx.x;   // b*H + j
    const int b = idx / H;
    const int j = idx % H;

    float gate[4];
#pragma unroll
    for (int g = 0; g < 4; g++) {
        const int o = b * 4 * H + g * H + j;
        float v = bias[g * H + j];
#pragma unroll
        for (int z = 0; z < PREZ; z++) v += pre[(long)z * pstride + o];
#pragma unroll
        for (int z = 0; z < KZ; z++) v += part[(long)z * (128 * 4 * H) + o];
        gate[g] = v;
    }

    const float cold = c[idx];
    const float cn = sigmoidf_(gate[1]) * cold + sigmoidf_(gate[0]) * tanhf(gate[2]);
    const float hn = sigmoidf_(gate[3]) * tanhf(cn);

    c[idx] = cn;
    __nv_bfloat16 hv = __float2bfloat16(hn);
    hhi[idx] = hv;
    hlo[idx] = __float2bfloat16(hn - __bfloat162float(hv));
    if (L2OUT) out[idx] = hn;
}

// ---------------------------------------------------------------------------
extern "C" void kernel_launch(void* const* d_in, const int* in_sizes, int n_in,
                              void* d_out, int out_size)
{
    const float* inp  = (const float*)d_in[0];   // [128,16,12288] flat [2048,12288]
    const float* Wih1 = (const float*)d_in[1];   // [1024,12288]
    const float* Whh1 = (const float*)d_in[2];   // [1024,256]
    const float* b1   = (const float*)d_in[3];   // [1024]
    const float* Wih2 = (const float*)d_in[4];   // [2048,256]
    const float* Whh2 = (const float*)d_in[5];   // [2048,512]
    const float* b2   = (const float*)d_in[6];   // [2048]
    float* out = (float*)d_out;                  // [16,128,512] flat

    __half *Xhi, *Xlo, *W1h;
    __nv_bfloat16 *W2hi, *W2lo;
    __nv_bfloat16 *R1hi, *R1lo, *R2hi, *R2lo, *y1hi, *y1lo, *h2hi, *h2lo;
    float *pre1, *pre2, *part1, *part2, *c1, *c2;
    cudaGetSymbolAddress((void**)&Xhi,  g_Xhi);
    cudaGetSymbolAddress((void**)&Xlo,  g_Xlo);
    cudaGetSymbolAddress((void**)&W1h,  g_W1h);
    cudaGetSymbolAddress((void**)&W2hi, g_W2hi);
    cudaGetSymbolAddress((void**)&W2lo, g_W2lo);
    cudaGetSymbolAddress((void**)&R1hi, g_Whh1hi);
    cudaGetSymbolAddress((void**)&R1lo, g_Whh1lo);
    cudaGetSymbolAddress((void**)&R2hi, g_Whh2hi);
    cudaGetSymbolAddress((void**)&R2lo, g_Whh2lo);
    cudaGetSymbolAddress((void**)&y1hi, g_y1hi);
    cudaGetSymbolAddress((void**)&y1lo, g_y1lo);
    cudaGetSymbolAddress((void**)&h2hi, g_h2hi);
    cudaGetSymbolAddress((void**)&h2lo, g_h2lo);
    cudaGetSymbolAddress((void**)&pre1, g_pre1);
    cudaGetSymbolAddress((void**)&pre2, g_pre2);
    cudaGetSymbolAddress((void**)&part1, g_part1);
    cudaGetSymbolAddress((void**)&part2, g_part2);
    cudaGetSymbolAddress((void**)&c1, g_c1);
    cudaGetSymbolAddress((void**)&c2, g_c2);

    cudaFuncSetAttribute(gemm_bf16split,
                         cudaFuncAttributeMaxDynamicSharedMemorySize, GSMEM_TOTAL);
    cudaFuncSetAttribute(gemm_f16_2term,
                         cudaFuncAttributeMaxDynamicSharedMemorySize, FSMEM_TOTAL);

    // 0) fresh recurrent state (h slice 0 = 0, c = 0)
    zero_states_kernel<<<256, 256>>>();

    // 1) precision conversions
    split_f16_kernel<<<(2048 * 12288 / 4 + 255) / 256, 256>>>(inp, Xhi, Xlo, 2048 * 12288 / 4);
    quant_f16_kernel<<<(1024 * 12288 / 4 + 255) / 256, 256>>>(Wih1, W1h, 1024 * 12288 / 4);
    split_kernel<<<(2048 * 256 / 4 + 255) / 256, 256>>>(Wih2, W2hi, W2lo, 2048 * 256 / 4);
    split_kernel<<<(1024 * 256 / 4 + 255) / 256, 256>>>(Whh1, R1hi, R1lo, 1024 * 256 / 4);
    split_kernel<<<(2048 * 512 / 4 + 255) / 256, 256>>>(Whh2, R2hi, R2lo, 2048 * 512 / 4);

    // 2) layer-1 input projection (fp16 2-term HMMA, K-split x2): pre1[2][2048,1024]
    gemm_f16_2term<<<dim3(8, 16, 2), 256, FSMEM_TOTAL>>>(
        Xhi, Xlo, W1h, pre1, 1024, IN_DIM, IN_DIM / 2, (long)2048 * 1024);

    // 3) layer-1 recurrence: per step, HMMA k-split partial GEMM + gates
    for (int t = 0; t < T_STEPS; t++) {
        gemm_bf16split<<<dim3(8, 1, 8), 256, GSMEM_TOTAL>>>(
            y1hi + (long)t * 128 * H1_DIM, y1lo + (long)t * 128 * H1_DIM,
            R1hi, R1lo, part1, 4 * H1_DIM, H1_DIM, H1_DIM / 8,
            (long)128 * 4 * H1_DIM);
        lstm_gates2<H1_DIM, 8, 2, false><<<BATCH * H1_DIM / 256, 256>>>(
            part1, pre1 + (long)t * 128 * 4 * H1_DIM, (long)2048 * 1024,
            b1, c1,
            y1hi + (long)(t + 1) * 128 * H1_DIM,
            y1lo + (long)(t + 1) * 128 * H1_DIM,
            nullptr);
    }

    // 4) layer-2 input projection (bf16 3-term HMMA): pre2[2048,2048]
    gemm_bf16split<<<dim3(16, 16, 1), 256, GSMEM_TOTAL>>>(
        y1hi + 128 * H1_DIM, y1lo + 128 * H1_DIM,
        W2hi, W2lo, pre2, 2048, H1_DIM, H1_DIM, 0);

    // 5) layer-2 recurrence -> d_out
    for (int t = 0; t < T_STEPS; t++) {
        gemm_bf16split<<<dim3(16, 1, 8), 256, GSMEM_TOTAL>>>(
            h2hi + (long)t * 128 * H2_DIM, h2lo + (long)t * 128 * H2_DIM,
            R2hi, R2lo, part2, 4 * H2_DIM, H2_DIM, H2_DIM / 8,
            (long)128 * 4 * H2_DIM);
        lstm_gates2<H2_DIM, 8, 1, true><<<BATCH * H2_DIM / 256, 256>>>(
            part2, pre2 + (long)t * 128 * 4 * H2_DIM, 0,
            b2, c2,
            h2hi + (long)(t + 1) * 128 * H2_DIM,
            h2lo + (long)(t + 1) * 128 * H2_DIM,
            out + (long)t * 128 * H2_DIM);
    }
}